// round 7
// baseline (speedup 1.0000x reference)
#include <cuda_runtime.h>
#include <mma.h>
#include <cstdint>
#include <math.h>

using namespace nvcuda;

#define BC    2
#define LSEQ  2048
#define HIDD  1024
#define NH    16
#define HD    64
#define PFF   4096
#define MROWS (BC * LSEQ)

// ---------------- device scratch ----------------
__device__ float g_q   [MROWS * HIDD];
__device__ float g_k   [MROWS * HIDD];
__device__ float g_v   [MROWS * HIDD];
__device__ float g_ao  [MROWS * HIDD];
__device__ float g_h   [MROWS * HIDD];
__device__ float g_hr  [MROWS * HIDD];
__device__ float g_ffn [(size_t)MROWS * PFF];
__device__ float g_wt  [16 * 1024 * 1024];
__device__ float g_tgtr[MROWS * HIDD];
__device__ float g_encr[MROWS * HIDD];

// ---------------- helpers ----------------
__device__ __forceinline__ void cp16(uint32_t dst, const float* src) {
    asm volatile("cp.async.cg.shared.global [%0], [%1], 16;"
        :: "r"(dst), "l"(__cvta_generic_to_global(src)));
}
__device__ __forceinline__ uint32_t smem_u32(const void* p) {
    uint32_t a;
    asm("{ .reg .u64 t; cvta.to.shared.u64 t, %1; cvt.u32.u64 %0, t; }"
        : "=r"(a) : "l"(p));
    return a;
}
__device__ __forceinline__ float rn32(float x) {
    unsigned u;
    asm("cvt.rna.tf32.f32 %0, %1;" : "=r"(u) : "f"(x));
    return __uint_as_float(u);
}

// ---------------------------------------------------------------------------
// Fused flash attention, 2-phase (exact softmax), tf32 HMMA.
// Block: 128 q-rows of head z.  Phase A: row max/sum.  Phase B: recompute S,
// P = exp(s-M)/L  (raw fp32 optionally written to Pout), rn-round P, O += P@V.
// Q,K,V in attn layout [z][l][64].  O -> row-major [b*LSEQ+q][h*64+d], rn32.
// ---------------------------------------------------------------------------
#define QS_  0
#define KS0_ 8704
#define KS1_ 17408
#define VS_  26112
#define SST_ 34816
#define MR_  51712
#define LR_  51840
#define MS_  51968
#define FL_SMEM (52096 * 4)

template<int WRITEP>
__global__ void __launch_bounds__(256)
flash_k(const float* __restrict__ Qg, const float* __restrict__ Kg,
        const float* __restrict__ Vg, const int* __restrict__ mask,
        float* __restrict__ Pout, float* __restrict__ Og)
{
    extern __shared__ float sm[];
    const uint32_t sb = smem_u32(sm);
    const int t = threadIdx.x, w = t >> 5;
    const int wy = w & 1, wx = w >> 1;
    const int z = blockIdx.y, b = z >> 4, h = z & 15;
    const int q0 = blockIdx.x * 128;

    const float* Qb = Qg + (size_t)z * LSEQ * HD;
    const float* Kb = Kg + (size_t)z * LSEQ * HD;
    const float* Vb = Vg + (size_t)z * LSEQ * HD;

    float* mrow = sm + MR_;
    float* lrow = sm + LR_;
    int*   msk  = (int*)(sm + MS_);

    // load Q tile (resident)
#pragma unroll
    for (int p = 0; p < 8; p++) {
        int idx = p * 256 + t, row = idx >> 4, c4 = (idx & 15) * 4;
        cp16(sb + (uint32_t)(QS_ + row * 68 + c4) * 4u,
             Qb + (size_t)(q0 + row) * HD + c4);
    }
    if (t < 128) { mrow[t] = -3.4e38f; lrow[t] = 0.f; }

    auto loadK = [&](int kt, int buf) {
        const float* src = Kb + (size_t)kt * 128 * HD;
        const uint32_t base = sb + (uint32_t)(buf ? KS1_ : KS0_) * 4u;
#pragma unroll
        for (int p = 0; p < 8; p++) {
            int idx = p * 256 + t, row = idx >> 4, c4 = (idx & 15) * 4;
            cp16(base + (uint32_t)(row * 68 + c4) * 4u, src + (size_t)row * HD + c4);
        }
    };
    auto loadV = [&](int kt) {
        const float* src = Vb + (size_t)kt * 128 * HD;
#pragma unroll
        for (int p = 0; p < 8; p++) {
            int idx = p * 256 + t, row = idx >> 4, c4 = (idx & 15) * 4;
            cp16(sb + (uint32_t)(VS_ + row * 68 + c4) * 4u, src + (size_t)row * HD + c4);
        }
    };

    auto do_qk = [&](int buf) {
        const float* Kst = sm + (buf ? KS1_ : KS0_);
        wmma::fragment<wmma::accumulator, 16, 16, 8, float> sf[4][2];
#pragma unroll
        for (int i = 0; i < 4; i++)
#pragma unroll
            for (int j = 0; j < 2; j++) wmma::fill_fragment(sf[i][j], 0.f);
#pragma unroll
        for (int ks = 0; ks < 8; ks++) {
            wmma::fragment<wmma::matrix_a, 16, 16, 8, wmma::precision::tf32, wmma::row_major> af[4];
#pragma unroll
            for (int fm = 0; fm < 4; fm++)
                wmma::load_matrix_sync(af[fm], sm + QS_ + (wy * 64 + fm * 16) * 68 + ks * 8, 68);
#pragma unroll
            for (int fn = 0; fn < 2; fn++) {
                wmma::fragment<wmma::matrix_b, 16, 16, 8, wmma::precision::tf32, wmma::col_major> bf;
                wmma::load_matrix_sync(bf, Kst + (wx * 32 + fn * 16) * 68 + ks * 8, 68);
#pragma unroll
                for (int fm = 0; fm < 4; fm++)
                    wmma::mma_sync(sf[fm][fn], af[fm], bf, sf[fm][fn]);
            }
        }
#pragma unroll
        for (int fm = 0; fm < 4; fm++)
#pragma unroll
            for (int fn = 0; fn < 2; fn++)
                wmma::store_matrix_sync(sm + SST_ + (wy * 64 + fm * 16) * 132 + wx * 32 + fn * 16,
                                        sf[fm][fn], 132, wmma::mem_row_major);
    };

    // ================= phase A: row stats =================
    asm volatile("cp.async.commit_group;");  // (empty group to simplify counting)
    loadK(0, 0);
    asm volatile("cp.async.commit_group;");
    for (int kt = 0; kt < 16; kt++) {
        if (kt < 15) {
            loadK(kt + 1, (kt + 1) & 1);
            asm volatile("cp.async.commit_group;");
            asm volatile("cp.async.wait_group 1;");
        } else {
            asm volatile("cp.async.wait_group 0;");
        }
        if (t < 128) msk[t] = mask[b * LSEQ + kt * 128 + t];
        __syncthreads();
        do_qk(kt & 1);
        __syncthreads();
        // stats: 2 threads per row
        {
            int row = t >> 1, half = t & 1;
            const float* Sp = sm + SST_ + row * 132 + half * 64;
            float tmax = -3.4e38f;
#pragma unroll
            for (int j = 0; j < 64; j += 4) {
                float4 v = *(const float4*)(Sp + j);
                float s0 = msk[half * 64 + j + 0] ? v.x * 0.125f : -1e30f;
                float s1 = msk[half * 64 + j + 1] ? v.y * 0.125f : -1e30f;
                float s2 = msk[half * 64 + j + 2] ? v.z * 0.125f : -1e30f;
                float s3 = msk[half * 64 + j + 3] ? v.w * 0.125f : -1e30f;
                tmax = fmaxf(tmax, fmaxf(fmaxf(s0, s1), fmaxf(s2, s3)));
            }
            tmax = fmaxf(tmax, __shfl_xor_sync(0xffffffffu, tmax, 1));
            float mold = mrow[row];
            float mnew = fmaxf(mold, tmax);
            float ssum = 0.f;
#pragma unroll
            for (int j = 0; j < 64; j += 4) {
                float4 v = *(const float4*)(Sp + j);
                float s0 = msk[half * 64 + j + 0] ? v.x * 0.125f : -1e30f;
                float s1 = msk[half * 64 + j + 1] ? v.y * 0.125f : -1e30f;
                float s2 = msk[half * 64 + j + 2] ? v.z * 0.125f : -1e30f;
                float s3 = msk[half * 64 + j + 3] ? v.w * 0.125f : -1e30f;
                ssum += __expf(s0 - mnew) + __expf(s1 - mnew)
                      + __expf(s2 - mnew) + __expf(s3 - mnew);
            }
            ssum += __shfl_xor_sync(0xffffffffu, ssum, 1);
            if (half == 0) {
                lrow[row] = lrow[row] * __expf(mold - mnew) + ssum;
                mrow[row] = mnew;
            }
        }
        __syncthreads();
    }
    if (t < 128) lrow[t] = 1.0f / lrow[t];
    __syncthreads();

    // ================= phase B: P + O accumulation =================
    wmma::fragment<wmma::accumulator, 16, 16, 8, float> of[4];
#pragma unroll
    for (int i = 0; i < 4; i++) wmma::fill_fragment(of[i], 0.f);

    loadK(0, 0);
    asm volatile("cp.async.commit_group;");
    for (int kt = 0; kt < 16; kt++) {
        loadV(kt);
        asm volatile("cp.async.commit_group;");
        if (kt < 15) {
            loadK(kt + 1, (kt + 1) & 1);
            asm volatile("cp.async.commit_group;");
            asm volatile("cp.async.wait_group 2;");   // K(kt) ready
        } else {
            asm volatile("cp.async.wait_group 1;");
        }
        if (t < 128) msk[t] = mask[b * LSEQ + kt * 128 + t];
        __syncthreads();
        do_qk(kt & 1);
        __syncthreads();
        // fused P compute + gmem write + rn-round (coalesced, 1 row per warp)
#pragma unroll
        for (int p = 0; p < 16; p++) {
            int idx = p * 256 + t, row = idx >> 5, c4 = (idx & 31) * 4;
            float mv = mrow[row], il = lrow[row];
            float4 v = *(const float4*)(sm + SST_ + row * 132 + c4);
            float s0 = msk[c4 + 0] ? v.x * 0.125f : -1e30f;
            float s1 = msk[c4 + 1] ? v.y * 0.125f : -1e30f;
            float s2 = msk[c4 + 2] ? v.z * 0.125f : -1e30f;
            float s3 = msk[c4 + 3] ? v.w * 0.125f : -1e30f;
            float4 pv;
            pv.x = __expf(s0 - mv) * il;
            pv.y = __expf(s1 - mv) * il;
            pv.z = __expf(s2 - mv) * il;
            pv.w = __expf(s3 - mv) * il;
            if (WRITEP)
                *(float4*)&Pout[(size_t)z * LSEQ * LSEQ + (size_t)(q0 + row) * LSEQ + kt * 128 + c4] = pv;
            pv.x = rn32(pv.x); pv.y = rn32(pv.y); pv.z = rn32(pv.z); pv.w = rn32(pv.w);
            *(float4*)(sm + SST_ + row * 132 + c4) = pv;
        }
        if (kt < 15) asm volatile("cp.async.wait_group 1;");   // V(kt) ready
        else         asm volatile("cp.async.wait_group 0;");
        __syncthreads();
        // O += P @ V
#pragma unroll
        for (int kk = 0; kk < 16; kk++) {
            wmma::fragment<wmma::matrix_a, 16, 16, 8, wmma::precision::tf32, wmma::row_major> af[4];
#pragma unroll
            for (int fm = 0; fm < 4; fm++)
                wmma::load_matrix_sync(af[fm], sm + SST_ + (wy * 64 + fm * 16) * 132 + kk * 8, 132);
            wmma::fragment<wmma::matrix_b, 16, 16, 8, wmma::precision::tf32, wmma::row_major> bf;
            wmma::load_matrix_sync(bf, sm + VS_ + kk * 8 * 68 + wx * 16, 68);
#pragma unroll
            for (int fm = 0; fm < 4; fm++)
                wmma::mma_sync(of[fm], af[fm], bf, of[fm]);
        }
        __syncthreads();
    }

    // write O: stage to smem then coalesced + rn32
#pragma unroll
    for (int fm = 0; fm < 4; fm++)
        wmma::store_matrix_sync(sm + SST_ + (wy * 64 + fm * 16) * 68 + wx * 16,
                                of[fm], 68, wmma::mem_row_major);
    __syncthreads();
#pragma unroll
    for (int p = 0; p < 8; p++) {
        int idx = p * 256 + t, row = idx >> 4, c4 = (idx & 15) * 4;
        float4 v = *(const float4*)(sm + SST_ + row * 68 + c4);
        v.x = rn32(v.x); v.y = rn32(v.y); v.z = rn32(v.z); v.w = rn32(v.w);
        *(float4*)&Og[((size_t)(b * LSEQ + q0 + row)) * HIDD + h * HD + c4] = v;
    }
}

// ---------------------------------------------------------------------------
// wmma tf32 dense GEMM (same as R6): D[128 x 256] = A[128,K] @ B[K,N]
// MODE 1: attn-layout + bias + rn     MODE 2: relu+bias+rn
// MODE 3: bias + residual row-major   MODE 7: fused QKV   MODE 8: fused KV
// ---------------------------------------------------------------------------
template<int MODE, int STAGES>
__global__ void __launch_bounds__(256)
tc_gemm(const float* __restrict__ A, const float* __restrict__ B,
        const float* __restrict__ bias0, const float* __restrict__ bias1,
        const float* __restrict__ bias2, const float* __restrict__ Rres,
        float* __restrict__ C0, float* __restrict__ C1, float* __restrict__ C2,
        int K, int lda, int ldb, int ncols)
{
    constexpr int NT = 256;
    constexpr int ABYTES = 128 * 36 * 4;
    constexpr int BBYTES = 32 * (NT + 4) * 4;
    constexpr int CHB = ABYTES + BBYTES;
    constexpr int STG_R = NT + 4;

    extern __shared__ float sm[];
    const uint32_t sb = smem_u32(sm);
    const int t = threadIdx.x, w = t >> 5;
    const int wy = w & 1, wx = w >> 1;
    const int m0 = blockIdx.y * 128, n0 = blockIdx.x * NT;

    const float* Ab = A;
    const float* Bb;
    if (MODE == 7 || MODE == 8)
        Bb = B + (size_t)(n0 >> 10) * 1048576 + (n0 & 1023);
    else
        Bb = B + n0;

    wmma::fragment<wmma::accumulator, 16, 16, 8, float> cf[4][4];
#pragma unroll
    for (int i = 0; i < 4; i++)
#pragma unroll
        for (int j = 0; j < 4; j++) wmma::fill_fragment(cf[i][j], 0.0f);

    auto load_chunk = [&](int ci, int s) {
        const int k0 = ci * 32;
        const uint32_t abase = sb + (uint32_t)(s * CHB);
#pragma unroll
        for (int j = 0; j < 4; j++) {
            int id = j * 256 + t, row = id >> 3, cc = id & 7;
            cp16(abase + (uint32_t)(row * 36 + cc * 4) * 4u,
                 Ab + (size_t)(m0 + row) * lda + k0 + cc * 4);
        }
        const uint32_t bbase = abase + ABYTES;
#pragma unroll
        for (int j = 0; j < 8; j++) {
            int id = j * 256 + t, row = id >> 6, c4 = id & 63;
            cp16(bbase + (uint32_t)(row * (NT + 4) + c4 * 4) * 4u,
                 Bb + (size_t)(k0 + row) * ldb + c4 * 4);
        }
        asm volatile("cp.async.commit_group;");
    };

    const int nch = K / 32;
#pragma unroll
    for (int s = 0; s < STAGES - 1; s++)
        if (s < nch) load_chunk(s, s);

    for (int i = 0; i < nch; i++) {
        if (i + STAGES - 1 < nch) load_chunk(i + STAGES - 1, (i + STAGES - 1) % STAGES);
        else asm volatile("cp.async.commit_group;");
        if (STAGES == 4) asm volatile("cp.async.wait_group 3;");
        else             asm volatile("cp.async.wait_group 2;");
        __syncthreads();
        const float* Ast = sm + (i % STAGES) * (CHB / 4);
        const float* Bst = Ast + ABYTES / 4;
#pragma unroll
        for (int ks = 0; ks < 4; ks++) {
            wmma::fragment<wmma::matrix_a, 16, 16, 8, wmma::precision::tf32, wmma::row_major> af[4];
#pragma unroll
            for (int fm = 0; fm < 4; fm++)
                wmma::load_matrix_sync(af[fm], Ast + (wy * 64 + fm * 16) * 36 + ks * 8, 36);
#pragma unroll
            for (int fn = 0; fn < 4; fn++) {
                wmma::fragment<wmma::matrix_b, 16, 16, 8, wmma::precision::tf32, wmma::row_major> bf;
                wmma::load_matrix_sync(bf, Bst + ks * 8 * (NT + 4) + wx * 64 + fn * 16, NT + 4);
#pragma unroll
                for (int fm = 0; fm < 4; fm++)
                    wmma::mma_sync(cf[fm][fn], af[fm], bf, cf[fm][fn]);
            }
        }
        __syncthreads();
    }
    __syncthreads();

    int em = (MODE == 7 || MODE == 8) ? 1 : MODE;
    int nrel = n0;
    const float* bb = bias0;
    float* Cc = C0;
    if (MODE == 7) {
        int seg = n0 >> 10; nrel = n0 & 1023;
        Cc = (seg == 0) ? C0 : (seg == 1) ? C1 : C2;
        bb = (seg == 0) ? bias0 : (seg == 1) ? bias1 : bias2;
    }
    if (MODE == 8) {
        int seg = n0 >> 10; nrel = n0 & 1023;
        Cc = seg ? C1 : C0;
        bb = seg ? bias1 : bias0;
    }

    float* stg = sm;
#pragma unroll
    for (int fm = 0; fm < 4; fm++)
#pragma unroll
        for (int fn = 0; fn < 4; fn++)
            wmma::store_matrix_sync(stg + (wy * 64 + fm * 16) * STG_R + wx * 64 + fn * 16,
                                    cf[fm][fn], STG_R, wmma::mem_row_major);
    __syncthreads();

#pragma unroll
    for (int p = 0; p < 32; p++) {
        int idx = p * 256 + t;
        int rr = idx >> 6;
        int cq = (idx & 63) * 4;
        float4 o = *(const float4*)&stg[rr * STG_R + cq];
        float vv[4] = {o.x, o.y, o.z, o.w};
#pragma unroll
        for (int c2 = 0; c2 < 4; c2++) {
            if (em == 1) vv[c2] = rn32(vv[c2] + __ldg(&bb[nrel + cq + c2]));
            if (em == 2) vv[c2] = rn32(fmaxf(vv[c2] + __ldg(&bb[n0 + cq + c2]), 0.f));
            if (em == 3) vv[c2] += __ldg(&bb[n0 + cq + c2]);
        }
        o.x = vv[0]; o.y = vv[1]; o.z = vv[2]; o.w = vv[3];
        if (em == 3) {
            const float4 rv = *(const float4*)&Rres[(size_t)(m0 + rr) * ncols + n0 + cq];
            o.x += rv.x; o.y += rv.y; o.z += rv.z; o.w += rv.w;
            *(float4*)&Cc[(size_t)(m0 + rr) * ncols + n0 + cq] = o;
        } else if (em == 1) {
            int m = m0 + rr, b = m >> 11, l = m & 2047;
            int nr = nrel + cq, h = nr >> 6, d = nr & 63;
            *(float4*)&Cc[(((size_t)(b * NH + h)) * LSEQ + l) * HD + d] = o;
        } else { // em == 2
            *(float4*)&Cc[(size_t)(m0 + rr) * ncols + n0 + cq] = o;
        }
    }
}

// ---------------------------------------------------------------------------
__global__ void __launch_bounds__(256)
roundcopy_k(const float4* s0, const float4* s1, const float4* s2, const float4* s3,
            const float4* s4, const float4* s5, const float4* s6, const float4* s7,
            const float4* f1, const float4* f2, const float4* tg, const float4* en,
            float4* wt, float4* tgtr, float4* encr)
{
    long long idx4 = (long long)blockIdx.x * 256 + threadIdx.x;
    const float4* src; float4* dst;
    if (idx4 < 2097152) {
        int wsel = (int)(idx4 >> 18);
        long long o = idx4 & 262143;
        const float4* s = (wsel == 0) ? s0 : (wsel == 1) ? s1 : (wsel == 2) ? s2 :
                          (wsel == 3) ? s3 : (wsel == 4) ? s4 : (wsel == 5) ? s5 :
                          (wsel == 6) ? s6 : s7;
        src = s + o; dst = wt + idx4;
    } else if (idx4 < 3145728) { src = f1 + (idx4 - 2097152); dst = wt + idx4; }
    else if (idx4 < 4194304)   { src = f2 + (idx4 - 3145728); dst = wt + idx4; }
    else if (idx4 < 5242880)   { long long o = idx4 - 4194304; src = tg + o; dst = tgtr + o; }
    else                       { long long o = idx4 - 5242880; src = en + o; dst = encr + o; }
    float4 v = *src;
    v.x = rn32(v.x); v.y = rn32(v.y); v.z = rn32(v.z); v.w = rn32(v.w);
    *dst = v;
}

// ---------------------------------------------------------------------------
__global__ void __launch_bounds__(256)
ln_k(const float* __restrict__ X, const float* __restrict__ gam,
     const float* __restrict__ bet, float* __restrict__ Y, float* __restrict__ Yr)
{
    const float* x = X + (size_t)blockIdx.x * HIDD;
    float*       y = Y + (size_t)blockIdx.x * HIDD;
    const int t = threadIdx.x;
    __shared__ float red[8];

    float v[4];
    float s = 0.f;
#pragma unroll
    for (int i = 0; i < 4; i++) { v[i] = x[t + 256 * i]; s += v[i]; }
#pragma unroll
    for (int o = 16; o; o >>= 1) s += __shfl_xor_sync(0xffffffffu, s, o);
    if ((t & 31) == 0) red[t >> 5] = s;
    __syncthreads();
    s = 0.f;
#pragma unroll
    for (int i = 0; i < 8; i++) s += red[i];
    const float mean = s * (1.0f / HIDD);

    float vs = 0.f;
#pragma unroll
    for (int i = 0; i < 4; i++) { float d = v[i] - mean; vs += d * d; }
#pragma unroll
    for (int o = 16; o; o >>= 1) vs += __shfl_xor_sync(0xffffffffu, vs, o);
    __syncthreads();
    if ((t & 31) == 0) red[t >> 5] = vs;
    __syncthreads();
    vs = 0.f;
#pragma unroll
    for (int i = 0; i < 8; i++) vs += red[i];
    const float inv = rsqrtf(vs * (1.0f / HIDD) + 1e-5f);

#pragma unroll
    for (int i = 0; i < 4; i++) {
        int c = t + 256 * i;
        float o = (v[i] - mean) * inv * gam[c] + bet[c];
        y[c] = o;
        if (Yr) Yr[(size_t)blockIdx.x * HIDD + c] = rn32(o);
    }
}

// ---------------------------------------------------------------------------
#define SMEM_D 206848   // 4 stages * (128*36 + 32*260) * 4B

extern "C" void kernel_launch(void* const* d_in, const int* in_sizes, int n_in,
                              void* d_out, int out_size)
{
    const float* tgt    = (const float*)d_in[0];
    const float* enc    = (const float*)d_in[1];
    const int*   tmask  = (const int*)  d_in[2];
    const int*   smask  = (const int*)  d_in[3];
    const float* sa_wq  = (const float*)d_in[4],  *sa_bq = (const float*)d_in[5];
    const float* sa_wk  = (const float*)d_in[6],  *sa_bk = (const float*)d_in[7];
    const float* sa_wv  = (const float*)d_in[8],  *sa_bv = (const float*)d_in[9];
    const float* sa_wo  = (const float*)d_in[10], *sa_bo = (const float*)d_in[11];
    const float* ea_wq  = (const float*)d_in[12], *ea_bq = (const float*)d_in[13];
    const float* ea_wk  = (const float*)d_in[14], *ea_bk = (const float*)d_in[15];
    const float* ea_wv  = (const float*)d_in[16], *ea_bv = (const float*)d_in[17];
    const float* ea_wo  = (const float*)d_in[18], *ea_bo = (const float*)d_in[19];
    const float* ffn_w1 = (const float*)d_in[20], *ffn_b1 = (const float*)d_in[21];
    const float* ffn_w2 = (const float*)d_in[22], *ffn_b2 = (const float*)d_in[23];
    const float* ln1_g  = (const float*)d_in[24], *ln1_b = (const float*)d_in[25];
    const float* ln2_g  = (const float*)d_in[26], *ln2_b = (const float*)d_in[27];
    const float* ln3_g  = (const float*)d_in[28], *ln3_b = (const float*)d_in[29];

    float* out     = (float*)d_out;
    float* att_out = out + (size_t)BC * LSEQ * HIDD;

    float *q, *k, *v, *ao, *h, *hr, *ffn, *wt, *tgtr, *encr;
    cudaGetSymbolAddress((void**)&q,    g_q);
    cudaGetSymbolAddress((void**)&k,    g_k);
    cudaGetSymbolAddress((void**)&v,    g_v);
    cudaGetSymbolAddress((void**)&ao,   g_ao);
    cudaGetSymbolAddress((void**)&h,    g_h);
    cudaGetSymbolAddress((void**)&hr,   g_hr);
    cudaGetSymbolAddress((void**)&ffn,  g_ffn);
    cudaGetSymbolAddress((void**)&wt,   g_wt);
    cudaGetSymbolAddress((void**)&tgtr, g_tgtr);
    cudaGetSymbolAddress((void**)&encr, g_encr);

    const size_t M1 = 1024 * 1024;

    cudaFuncSetAttribute(tc_gemm<7,4>, cudaFuncAttributeMaxDynamicSharedMemorySize, SMEM_D);
    cudaFuncSetAttribute(tc_gemm<8,4>, cudaFuncAttributeMaxDynamicSharedMemorySize, SMEM_D);
    cudaFuncSetAttribute(tc_gemm<1,4>, cudaFuncAttributeMaxDynamicSharedMemorySize, SMEM_D);
    cudaFuncSetAttribute(tc_gemm<2,4>, cudaFuncAttributeMaxDynamicSharedMemorySize, SMEM_D);
    cudaFuncSetAttribute(tc_gemm<3,4>, cudaFuncAttributeMaxDynamicSharedMemorySize, SMEM_D);
    cudaFuncSetAttribute(flash_k<0>,   cudaFuncAttributeMaxDynamicSharedMemorySize, FL_SMEM);
    cudaFuncSetAttribute(flash_k<1>,   cudaFuncAttributeMaxDynamicSharedMemorySize, FL_SMEM);

    roundcopy_k<<<24576, 256>>>(
        (const float4*)sa_wq, (const float4*)sa_wk, (const float4*)sa_wv, (const float4*)sa_wo,
        (const float4*)ea_wq, (const float4*)ea_wk, (const float4*)ea_wv, (const float4*)ea_wo,
        (const float4*)ffn_w1, (const float4*)ffn_w2, (const float4*)tgt, (const float4*)enc,
        (float4*)wt, (float4*)tgtr, (float4*)encr);

    float* w_saq = wt + 0 * M1; float* w_sao = wt + 3 * M1;
    float* w_eaq = wt + 4 * M1; float* w_eak = wt + 5 * M1; float* w_eao = wt + 7 * M1;
    float* w_f1  = wt + 8 * M1; float* w_f2  = wt + 12 * M1;

    const dim3 gqkv(12, 32);
    const dim3 gkv (8, 32);
    const dim3 gp  (4, 32);
    const dim3 gf1 (16, 32);
    const dim3 gfl (16, 32);

    // ---- self-attention (fully fused attention core) ----
    tc_gemm<7,4><<<gqkv, 256, SMEM_D>>>(tgtr, w_saq, sa_bq, sa_bk, sa_bv, nullptr,
                                        q, k, v, 1024, 1024, 1024, 1024);
    flash_k<0><<<gfl, 256, FL_SMEM>>>(q, k, v, tmask, nullptr, ao);
    tc_gemm<3,4><<<gp, 256, SMEM_D>>>(ao, w_sao, sa_bo, nullptr, nullptr, tgt,
                                      h, nullptr, nullptr, 1024, 1024, 1024, 1024);
    ln_k<<<MROWS, 256>>>(h, ln1_g, ln1_b, h, hr);

    // ---- cross-attention (probs written by flash directly into d_out) ----
    tc_gemm<1,4><<<gp, 256, SMEM_D>>>(hr, w_eaq, ea_bq, nullptr, nullptr, nullptr,
                                      q, nullptr, nullptr, 1024, 1024, 1024, 1024);
    tc_gemm<8,4><<<gkv, 256, SMEM_D>>>(encr, w_eak, ea_bk, ea_bv, nullptr, nullptr,
                                       k, v, nullptr, 1024, 1024, 1024, 1024);
    flash_k<1><<<gfl, 256, FL_SMEM>>>(q, k, v, smask, att_out, ao);
    tc_gemm<3,4><<<gp, 256, SMEM_D>>>(ao, w_eao, ea_bo, nullptr, nullptr, h,
                                      h, nullptr, nullptr, 1024, 1024, 1024, 1024);
    ln_k<<<MROWS, 256>>>(h, ln2_g, ln2_b, h, hr);

    // ---- FFN ----
    tc_gemm<2,4><<<gf1, 256, SMEM_D>>>(hr, w_f1, ffn_b1, nullptr, nullptr, nullptr,
                                       ffn, nullptr, nullptr, 1024, 1024, 4096, 4096);
    tc_gemm<3,4><<<gp, 256, SMEM_D>>>(ffn, w_f2, ffn_b2, nullptr, nullptr, h,
                                      h, nullptr, nullptr, 4096, 4096, 1024, 1024);
    ln_k<<<MROWS, 256>>>(h, ln3_g, ln3_b, out, nullptr);
}